// round 1
// baseline (speedup 1.0000x reference)
#include <cuda_runtime.h>
#include <math.h>

// Problem constants (from reference):
//   input_feats: [B=8, L=4096, C=2048] fp32   (H = W = 64)
//   points_yx:   [B=8, M=4, P=512, 2] fp32
//   output:      [B=8, M=4, O=64, C=2048] fp32, O = POOL_OUT, k = P/O = 8
//
// out[b,m,o,c] = (1/8) * sum_{p in chunk o} bilinear_sample(feat[b], p)[c]
//             = sum_{j=0..31} w_j * feat[b, idx_j, c]
// where the 32 (idx_j, w_j) pairs are the 4 bilinear corners of the 8 points
// in chunk o, with weights already divided by 8.

#define H 64
#define W 64
#define C 2048
#define CV4 (C / 4)          // 512 float4 per feature row
#define M_MASKS 4
#define P_PTS 512
#define O_POOL 64
#define KCHUNK 8             // points per pooled output
#define NPAIR 32             // KCHUNK * 4 corners

__global__ __launch_bounds__(256, 8)
void point_sample_pool_kernel(const float* __restrict__ feats,
                              const float* __restrict__ pts,
                              float* __restrict__ out)
{
    // blockIdx.x in [0, B*M*O) = [0, 2048)
    const int bmo = blockIdx.x;
    const int o   = bmo & (O_POOL - 1);
    const int bm  = bmo >> 6;            // b*4 + m, in [0, 32)
    const int b   = bm >> 2;

    __shared__ int   s_idx[NPAIR];
    __shared__ float s_w[NPAIR];

    const int tid = threadIdx.x;

    if (tid < NPAIR) {
        const int p_local = tid >> 2;    // which point in the chunk (0..7)
        const int corner  = tid & 3;     // 0:(y0,x0) 1:(y0,x1) 2:(y1,x0) 3:(y1,x1)
        const int p = o * KCHUNK + p_local;
        const float* pp = pts + ((size_t)bm * P_PTS + p) * 2;
        const float iy = pp[0] * (float)(H - 1);
        const float ix = pp[1] * (float)(W - 1);
        const float y0f = floorf(iy);
        const float x0f = floorf(ix);
        const float wy = iy - y0f;
        const float wx = ix - x0f;
        int y0 = (int)y0f; y0 = max(0, min(y0, H - 1));
        int x0 = (int)x0f; x0 = max(0, min(x0, W - 1));
        const int y1 = min(y0 + 1, H - 1);
        const int x1 = min(x0 + 1, W - 1);

        const int   yi  = (corner & 2) ? y1 : y0;
        const int   xi  = (corner & 1) ? x1 : x0;
        const float wyc = (corner & 2) ? wy : (1.0f - wy);
        const float wxc = (corner & 1) ? wx : (1.0f - wx);

        s_idx[tid] = yi * W + xi;
        s_w[tid]   = wyc * wxc * (1.0f / (float)KCHUNK);
    }
    __syncthreads();

    const float4* base = (const float4*)(feats + (size_t)b * (H * W) * C);

    // 512 float4 per output row; 256 threads -> 2 float4 each
    const int c0 = tid;
    const int c1 = tid + 256;

    float4 acc0 = make_float4(0.f, 0.f, 0.f, 0.f);
    float4 acc1 = make_float4(0.f, 0.f, 0.f, 0.f);

    #pragma unroll
    for (int j = 0; j < NPAIR; j++) {
        const float  w   = s_w[j];
        const float4* row = base + (size_t)s_idx[j] * CV4;
        const float4 v0 = __ldg(&row[c0]);
        const float4 v1 = __ldg(&row[c1]);
        acc0.x = fmaf(w, v0.x, acc0.x);
        acc0.y = fmaf(w, v0.y, acc0.y);
        acc0.z = fmaf(w, v0.z, acc0.z);
        acc0.w = fmaf(w, v0.w, acc0.w);
        acc1.x = fmaf(w, v1.x, acc1.x);
        acc1.y = fmaf(w, v1.y, acc1.y);
        acc1.z = fmaf(w, v1.z, acc1.z);
        acc1.w = fmaf(w, v1.w, acc1.w);
    }

    float4* op = (float4*)(out + (size_t)bmo * C);
    op[c0] = acc0;
    op[c1] = acc1;
}

extern "C" void kernel_launch(void* const* d_in, const int* in_sizes, int n_in,
                              void* d_out, int out_size)
{
    const float* feats = (const float*)d_in[0];   // [8,4096,2048]
    const float* pts   = (const float*)d_in[1];   // [8,4,512,2]
    float* out = (float*)d_out;                    // [8,4,64,2048]

    const int grid = 8 * M_MASKS * O_POOL;         // 2048 CTAs
    point_sample_pool_kernel<<<grid, 256>>>(feats, pts, out);
}

// round 2
// speedup vs baseline: 1.1243x; 1.1243x over previous
#include <cuda_runtime.h>
#include <math.h>

// input_feats: [B=8, L=4096, C=2048] fp32   (H = W = 64)
// points_yx:   [B=8, M=4, P=512, 2] fp32
// output:      [B=8, M=4, O=64, C=2048] fp32, O = POOL_OUT, k = P/O = 8
//
// out[b,m,o,c] = sum_{j=0..31} w_j * feat[b, idx_j, c]
// (32 pairs = 8 points x 4 bilinear corners, weights pre-divided by 8)
//
// Round-2 change: 2 CTAs per output row (channel halves) -> 512 CTAs per
// batch -> the ~1184-CTA concurrency window spans only ~2.3 batches
// (~70 MB) which fits in the 126 MB L2, eliminating DRAM re-fetch of
// feature rows. Output written with streaming stores to avoid polluting L2.

#define H 64
#define W 64
#define C 2048
#define CV4 (C / 4)          // 512 float4 per feature row
#define M_MASKS 4
#define P_PTS 512
#define O_POOL 64
#define KCHUNK 8
#define NPAIR 32

__global__ __launch_bounds__(256, 8)
void point_sample_pool_kernel(const float* __restrict__ feats,
                              const float* __restrict__ pts,
                              float* __restrict__ out)
{
    // blockIdx.x in [0, 4096): bmo*2 + half  (b-major ordering preserved)
    const int half = blockIdx.x & 1;
    const int bmo  = blockIdx.x >> 1;        // [0, 2048)
    const int o    = bmo & (O_POOL - 1);
    const int bm   = bmo >> 6;               // b*4 + m
    const int b    = bm >> 2;

    __shared__ int   s_idx[NPAIR];
    __shared__ float s_w[NPAIR];

    const int tid = threadIdx.x;

    if (tid < NPAIR) {
        const int p_local = tid >> 2;
        const int corner  = tid & 3;
        const int p = o * KCHUNK + p_local;
        const float* pp = pts + ((size_t)bm * P_PTS + p) * 2;
        const float iy = pp[0] * (float)(H - 1);
        const float ix = pp[1] * (float)(W - 1);
        const float y0f = floorf(iy);
        const float x0f = floorf(ix);
        const float wy = iy - y0f;
        const float wx = ix - x0f;
        int y0 = (int)y0f; y0 = max(0, min(y0, H - 1));
        int x0 = (int)x0f; x0 = max(0, min(x0, W - 1));
        const int y1 = min(y0 + 1, H - 1);
        const int x1 = min(x0 + 1, W - 1);

        const int   yi  = (corner & 2) ? y1 : y0;
        const int   xi  = (corner & 1) ? x1 : x0;
        const float wyc = (corner & 2) ? wy : (1.0f - wy);
        const float wxc = (corner & 1) ? wx : (1.0f - wx);

        s_idx[tid] = yi * W + xi;
        s_w[tid]   = wyc * wxc * (1.0f / (float)KCHUNK);
    }
    __syncthreads();

    const float4* base = (const float4*)(feats + (size_t)b * (H * W) * C);

    // This CTA owns float4 slots [half*256, half*256+256)
    const int c4 = half * 256 + tid;

    float4 acc = make_float4(0.f, 0.f, 0.f, 0.f);

    #pragma unroll
    for (int j = 0; j < NPAIR; j++) {
        const float  w = s_w[j];
        const float4 v = __ldg(&((base + (size_t)s_idx[j] * CV4)[c4]));
        acc.x = fmaf(w, v.x, acc.x);
        acc.y = fmaf(w, v.y, acc.y);
        acc.z = fmaf(w, v.z, acc.z);
        acc.w = fmaf(w, v.w, acc.w);
    }

    // Streaming store: output is never re-read; keep it out of L2's way.
    float4* op = (float4*)(out + (size_t)bmo * C) + c4;
    __stcs(op, acc);
}

extern "C" void kernel_launch(void* const* d_in, const int* in_sizes, int n_in,
                              void* d_out, int out_size)
{
    const float* feats = (const float*)d_in[0];
    const float* pts   = (const float*)d_in[1];
    float* out = (float*)d_out;

    const int grid = 8 * M_MASKS * O_POOL * 2;   // 4096 CTAs
    point_sample_pool_kernel<<<grid, 256>>>(feats, pts, out);
}

// round 3
// speedup vs baseline: 1.1757x; 1.0457x over previous
#include <cuda_runtime.h>
#include <math.h>

// input_feats: [B=8, L=4096, C=2048] fp32   (H = W = 64)
// points_yx:   [B=8, M=4, P=512, 2] fp32
// output:      [B=8, M=4, O=64, C=2048] fp32
//
// out[b,m,o,c] = sum_{j=0..31} w_j * feat[b, idx_j, c]
//
// Round-3 change: raise per-thread MLP. 64-reg budget (launch_bounds 256,4)
// + explicit batches of 8 float4 loads before their FMAs -> MLP_p1 ~ 8.
// DRAM traffic is already at the unique-footprint floor (~250 MB); the goal
// is pushing DRAM utilization from 70% toward 85%.

#define H 64
#define W 64
#define C 2048
#define CV4 (C / 4)
#define M_MASKS 4
#define P_PTS 512
#define O_POOL 64
#define KCHUNK 8
#define NPAIR 32
#define UF 8                 // load batch size (8 x float4 = 32 regs)

__global__ __launch_bounds__(256, 4)
void point_sample_pool_kernel(const float* __restrict__ feats,
                              const float* __restrict__ pts,
                              float* __restrict__ out)
{
    // blockIdx.x in [0, 4096): bmo*2 + half (b-major ordering preserved)
    const int half = blockIdx.x & 1;
    const int bmo  = blockIdx.x >> 1;
    const int o    = bmo & (O_POOL - 1);
    const int bm   = bmo >> 6;               // b*4 + m
    const int b    = bm >> 2;

    __shared__ int   s_idx[NPAIR];
    __shared__ float s_w[NPAIR];

    const int tid = threadIdx.x;

    if (tid < NPAIR) {
        const int p_local = tid >> 2;
        const int corner  = tid & 3;
        const int p = o * KCHUNK + p_local;
        const float* pp = pts + ((size_t)bm * P_PTS + p) * 2;
        const float iy = pp[0] * (float)(H - 1);
        const float ix = pp[1] * (float)(W - 1);
        const float y0f = floorf(iy);
        const float x0f = floorf(ix);
        const float wy = iy - y0f;
        const float wx = ix - x0f;
        int y0 = (int)y0f; y0 = max(0, min(y0, H - 1));
        int x0 = (int)x0f; x0 = max(0, min(x0, W - 1));
        const int y1 = min(y0 + 1, H - 1);
        const int x1 = min(x0 + 1, W - 1);

        const int   yi  = (corner & 2) ? y1 : y0;
        const int   xi  = (corner & 1) ? x1 : x0;
        const float wyc = (corner & 2) ? wy : (1.0f - wy);
        const float wxc = (corner & 1) ? wx : (1.0f - wx);

        s_idx[tid] = yi * W + xi;
        s_w[tid]   = wyc * wxc * (1.0f / (float)KCHUNK);
    }
    __syncthreads();

    const float4* base = (const float4*)(feats + (size_t)b * (H * W) * C) ;

    // This CTA owns float4 slots [half*256, half*256+256)
    const int c4 = half * 256 + tid;

    float4 acc0 = make_float4(0.f, 0.f, 0.f, 0.f);
    float4 acc1 = make_float4(0.f, 0.f, 0.f, 0.f);

    #pragma unroll
    for (int j0 = 0; j0 < NPAIR; j0 += UF) {
        float4 v[UF];
        // Front-batch UF independent loads (MLP_p1 = UF)
        #pragma unroll
        for (int u = 0; u < UF; u++) {
            v[u] = __ldg(base + (size_t)s_idx[j0 + u] * CV4 + c4);
        }
        // Then consume
        #pragma unroll
        for (int u = 0; u < UF; u++) {
            const float w = s_w[j0 + u];
            float4& a = (u & 1) ? acc1 : acc0;
            a.x = fmaf(w, v[u].x, a.x);
            a.y = fmaf(w, v[u].y, a.y);
            a.z = fmaf(w, v[u].z, a.z);
            a.w = fmaf(w, v[u].w, a.w);
        }
    }

    acc0.x += acc1.x; acc0.y += acc1.y; acc0.z += acc1.z; acc0.w += acc1.w;

    // Streaming store: output is never re-read.
    float4* op = (float4*)(out + (size_t)bmo * C) + c4;
    __stcs(op, acc0);
}

extern "C" void kernel_launch(void* const* d_in, const int* in_sizes, int n_in,
                              void* d_out, int out_size)
{
    const float* feats = (const float*)d_in[0];
    const float* pts   = (const float*)d_in[1];
    float* out = (float*)d_out;

    const int grid = 8 * M_MASKS * O_POOL * 2;   // 4096 CTAs
    point_sample_pool_kernel<<<grid, 256>>>(feats, pts, out);
}